// round 9
// baseline (speedup 1.0000x reference)
#include <cuda_runtime.h>
#include <cuda_fp16.h>
#include <math.h>

// Problem constants (fixed-shape problem)
#define BB   16
#define NN   2048
#define DD   64
#define EE   32768
#define MAXK 128
#define ROWS (BB*NN)          // 32768
#define TBL  128
#define BR   32               // rows per gemm block

// Scratch (device globals; zero-initialized at module load; no allocation)
__device__ int      g_cnt_raw[ROWS];                 // scatter counters (reset by dedup)
__device__ int      g_nnz[ROWS];                     // padded row sizes (multiple of 8)
__device__ uint2    g_bucket[(size_t)ROWS * MAXK];   // 32 MB (col<<17|pri, m_bits)
__device__ float    g_dis[ROWS];
__device__ uint2    g_adj[(size_t)ROWS * MAXK];      // 32 MB (col<<7 byte-off, m_bits)
__device__ __half2  g_x [(size_t)ROWS * 32];         // 4 MB: dis ⊙ H   (layer 0 input)
__device__ __half2  g_x1[(size_t)ROWS * 32];         // 4 MB: dis ⊙ x1  (layer 1 input)
__device__ float2   g_pre[(size_t)ROWS * 32];        // 8 MB: dis_r * (A·X~ + X~row)

// ---- packed f32x2 helpers (Blackwell) --------------------------------------
__device__ __forceinline__ unsigned long long splat2(float x) {
    unsigned long long r;
    asm("mov.b64 %0, {%1, %1};" : "=l"(r) : "r"(__float_as_uint(x)));
    return r;
}
__device__ __forceinline__ void fma2(unsigned long long& d,
                                     unsigned long long a, unsigned long long b) {
    asm("fma.rn.f32x2 %0, %1, %2, %0;" : "+l"(d) : "l"(a), "l"(b));
}
__device__ __forceinline__ float2 unpack2(unsigned long long v) {
    unsigned lo, hi;
    asm("mov.b64 {%0, %1}, %2;" : "=r"(lo), "=r"(hi) : "l"(v));
    return make_float2(__uint_as_float(lo), __uint_as_float(hi));
}

// ---------------------------------------------------------------------------
// scatter directed entries into per-row buckets, carrying m (coalesced read).
// key = (col << 17) | priority, priority = pass*E + e (pass2 > pass1)
__global__ void scatter_k(const int* __restrict__ ei, const float* __restrict__ m) {
    int t = blockIdx.x * blockDim.x + threadIdx.x;
    int b = t >> 15;
    int e = t & (EE - 1);
    int src = ei[b * 2 * EE + e];
    int dst = ei[b * 2 * EE + EE + e];
    unsigned mbits = __float_as_uint(m[t]);

    int r1 = b * NN + src;
    int p1 = atomicAdd(&g_cnt_raw[r1], 1);
    if (p1 < MAXK)
        g_bucket[(size_t)r1 * MAXK + p1] = make_uint2(((unsigned)dst << 17) | (unsigned)e, mbits);

    int r2 = b * NN + dst;
    int p2 = atomicAdd(&g_cnt_raw[r2], 1);
    if (p2 < MAXK)
        g_bucket[(size_t)r2 * MAXK + p2] = make_uint2(((unsigned)src << 17) | (unsigned)(EE + e), mbits);
}

// ---------------------------------------------------------------------------
// O(k) hash dedup (exact .set last-write-wins via 64-bit atomicMax on
// (col<<17|pri) in high word), ballot compaction into zero-padded CSR storing
// BYTE OFFSETS (col*128), deg -> dis = rsqrt(deg), AND prep: g_x = half(dis ⊙ H).
// Resets g_cnt_raw. One warp per row, 8 rows per block.
__global__ void __launch_bounds__(256) dedup_k(const float* __restrict__ H) {
    __shared__ unsigned long long tbl[8][TBL];
    int wid  = threadIdx.x >> 5, lane = threadIdx.x & 31;
    int row  = blockIdx.x * 8 + wid;

    for (int i = lane; i < TBL; i += 32) tbl[wid][i] = 0ULL;
    __syncwarp();

    int k = g_cnt_raw[row];
    if (k > MAXK) k = MAXK;
    const uint2* src = &g_bucket[(size_t)row * MAXK];
    for (int t = lane; t < k; t += 32) {
        uint2 v = src[t];
        unsigned col = v.x >> 17;
        unsigned long long val = ((unsigned long long)v.x << 32) | (unsigned long long)v.y;
        unsigned h = col & (TBL - 1);
        while (true) {
            unsigned long long cur = tbl[wid][h];
            if (cur == 0ULL) {
                unsigned long long old = atomicCAS(&tbl[wid][h], 0ULL, val);
                if (old == 0ULL) break;
                cur = old;
            }
            if ((unsigned)(cur >> 49) == col) {       // same col -> keep max priority
                atomicMax(&tbl[wid][h], val);
                break;
            }
            h = (h + 1) & (TBL - 1);
        }
    }
    __syncwarp();

    // compact + degree sum; store byte offset col*128 (fp16 row = 128B)
    float deg = 0.f;
    int base = 0;
    uint2* dst = &g_adj[(size_t)row * MAXK];
    #pragma unroll
    for (int s0 = 0; s0 < TBL; s0 += 32) {
        unsigned long long cur = tbl[wid][s0 + lane];
        bool has = (cur != 0ULL);
        unsigned bal = __ballot_sync(0xFFFFFFFFu, has);
        if (has) {
            int pos = base + __popc(bal & ((1u << lane) - 1));
            unsigned col = ((unsigned)(cur >> 32)) >> 17;
            unsigned mb  = (unsigned)cur;
            dst[pos] = make_uint2(col << 7, mb);
            deg += __uint_as_float(mb);
        }
        base += __popc(bal);
    }
    // zero padding up to multiple of 8 (beyond stays zero from static init;
    // replays rewrite identical data so zero region is invariant)
    int pad = (base + 7) & ~7;
    if (base + lane < pad) dst[base + lane] = make_uint2(0u, 0u);

    // all-lanes deg reduction -> dis on every lane
    #pragma unroll
    for (int o = 16; o; o >>= 1) deg += __shfl_xor_sync(0xFFFFFFFFu, deg, o);
    float dis = rsqrtf(fmaxf(1.0f + deg, 1e-6f));

    // prep: g_x[row] = half(dis * H[row])
    const float2* Hrow = (const float2*)H + row * 32;
    float2 h2 = Hrow[lane];
    g_x[row * 32 + lane] = __floats2half2_rn(dis * h2.x, dis * h2.y);

    if (lane == 0) {
        g_nnz[row] = pad;
        g_dis[row] = dis;
        g_cnt_raw[row] = 0;     // ready for next replay
    }
}

// ---------------------------------------------------------------------------
// SpMM phase: pre[row] = dis_r * (sum_e m_e * X~[col] + X~[row]).
// TWO warps per row (even/odd 8-edge chunks, smem combine): halves the serial
// dependent-gather chain and doubles resident warps. Adjacency for the next
// chunk is prefetched so only the gathers sit on the critical path.
__global__ void __launch_bounds__(256) spmm_k(int stage) {
    const __half2* Xin = (stage == 0) ? g_x : g_x1;
    __shared__ float2 part[4][32];

    int wid = threadIdx.x >> 5, lane = threadIdx.x & 31;
    int rl = wid >> 1, half = wid & 1;
    int row = blockIdx.x * 4 + rl;

    const char* XbL = (const char*)(Xin + (row & ~(NN - 1)) * 32) + lane * 4;
    const uint2* arow = &g_adj[(size_t)row * MAXK];
    int n = g_nnz[row];                                 // multiple of 8

    float2 a = make_float2(0.f, 0.f);
    int k = half * 8;
    if (k < n) {
        uint4 e0 = *(const uint4*)(arow + k);
        uint4 e1 = *(const uint4*)(arow + k + 2);
        uint4 e2 = *(const uint4*)(arow + k + 4);
        uint4 e3 = *(const uint4*)(arow + k + 6);
        while (true) {
            int kn = k + 16;
            bool more = kn < n;
            int kp = more ? kn : 0;
            uint4 f0 = *(const uint4*)(arow + kp);
            uint4 f1 = *(const uint4*)(arow + kp + 2);
            uint4 f2 = *(const uint4*)(arow + kp + 4);
            uint4 f3 = *(const uint4*)(arow + kp + 6);

            __half2 x0 = *(const __half2*)(XbL + e0.x);
            __half2 x1 = *(const __half2*)(XbL + e0.z);
            __half2 x2 = *(const __half2*)(XbL + e1.x);
            __half2 x3 = *(const __half2*)(XbL + e1.z);
            __half2 x4 = *(const __half2*)(XbL + e2.x);
            __half2 x5 = *(const __half2*)(XbL + e2.z);
            __half2 x6 = *(const __half2*)(XbL + e3.x);
            __half2 x7 = *(const __half2*)(XbL + e3.z);

            float2 f;
            f = __half22float2(x0); a.x += __uint_as_float(e0.y) * f.x; a.y += __uint_as_float(e0.y) * f.y;
            f = __half22float2(x1); a.x += __uint_as_float(e0.w) * f.x; a.y += __uint_as_float(e0.w) * f.y;
            f = __half22float2(x2); a.x += __uint_as_float(e1.y) * f.x; a.y += __uint_as_float(e1.y) * f.y;
            f = __half22float2(x3); a.x += __uint_as_float(e1.w) * f.x; a.y += __uint_as_float(e1.w) * f.y;
            f = __half22float2(x4); a.x += __uint_as_float(e2.y) * f.x; a.y += __uint_as_float(e2.y) * f.y;
            f = __half22float2(x5); a.x += __uint_as_float(e2.w) * f.x; a.y += __uint_as_float(e2.w) * f.y;
            f = __half22float2(x6); a.x += __uint_as_float(e3.y) * f.x; a.y += __uint_as_float(e3.y) * f.y;
            f = __half22float2(x7); a.x += __uint_as_float(e3.w) * f.x; a.y += __uint_as_float(e3.w) * f.y;

            if (!more) break;
            k = kn; e0 = f0; e1 = f1; e2 = f2; e3 = f3;
        }
    }

    if (half == 1) {
        part[rl][lane] = a;
    }
    __syncthreads();
    if (half == 0) {
        float2 p = part[rl][lane];
        float2 d = __half22float2(Xin[row * 32 + lane]);   // diag term X~row
        float dis = g_dis[row];
        g_pre[row * 32 + lane] =
            make_float2(dis * (a.x + p.x + d.x), dis * (a.y + p.y + d.y));
    }
}

// ---------------------------------------------------------------------------
// Dense GEMM phase: v = pre @ W^T, then (stage 0) g_x1 = half(dis * gelu(v))
// or (stage 1) out = v. 32 rows/block (grid 1024 -> ~7 blocks/SM), 256 threads,
// thread owns 2x4 outputs, packed fma.rn.f32x2 inner loop.
__global__ void __launch_bounds__(256) gemm_k(const float* __restrict__ Wl,
                                              float* __restrict__ out,
                                              int stage) {
    __shared__ float sP[BR][68];    // pre tile, row-major [r][d], padded
    __shared__ float sW[64][68];    // W transposed [d][e], padded
    int tid = threadIdx.x;
    int row0 = blockIdx.x * BR;

    // W[e][d] -> sW[d][e]  (coalesced gmem read)
    for (int idx = tid; idx < 4096; idx += 256) {
        int e = idx >> 6, d = idx & 63;
        sW[d][e] = Wl[idx];
    }
    // pre tile: straight float4 copy (row-major, no transpose)
    const float4* P = (const float4*)(g_pre + (size_t)row0 * 32);
    for (int idx = tid; idx < BR * 16; idx += 256) {
        int r = idx >> 4, d4 = idx & 15;
        *(float4*)&sP[r][d4 * 4] = P[idx];
    }
    __syncthreads();

    int rg = tid >> 4, cg = tid & 15;
    int r0 = rg * 2, c0 = cg * 4;

    unsigned long long acc[2][2];
    acc[0][0] = acc[0][1] = acc[1][0] = acc[1][1] = 0ULL;

    #pragma unroll
    for (int d0 = 0; d0 < 64; d0 += 4) {
        float4 p0 = *(const float4*)&sP[r0][d0];
        float4 p1 = *(const float4*)&sP[r0 + 1][d0];
        #pragma unroll
        for (int dd = 0; dd < 4; dd++) {
            unsigned long long w01 = *(const unsigned long long*)&sW[d0 + dd][c0];
            unsigned long long w23 = *(const unsigned long long*)&sW[d0 + dd][c0 + 2];
            unsigned long long s0 = splat2((&p0.x)[dd]);
            unsigned long long s1 = splat2((&p1.x)[dd]);
            fma2(acc[0][0], s0, w01);
            fma2(acc[0][1], s0, w23);
            fma2(acc[1][0], s1, w01);
            fma2(acc[1][1], s1, w23);
        }
    }

    #pragma unroll
    for (int r = 0; r < 2; r++) {
        int row = row0 + r0 + r;
        float2 v01 = unpack2(acc[r][0]);
        float2 v23 = unpack2(acc[r][1]);
        if (stage == 0) {
            // exact GELU, prescale by dis, store fp16 for next layer's gather
            float dis = g_dis[row];
            v01.x = 0.5f * v01.x * (1.f + erff(v01.x * 0.70710678118654752f));
            v01.y = 0.5f * v01.y * (1.f + erff(v01.y * 0.70710678118654752f));
            v23.x = 0.5f * v23.x * (1.f + erff(v23.x * 0.70710678118654752f));
            v23.y = 0.5f * v23.y * (1.f + erff(v23.y * 0.70710678118654752f));
            g_x1[row * 32 + (c0 >> 1)]     = __floats2half2_rn(dis * v01.x, dis * v01.y);
            g_x1[row * 32 + (c0 >> 1) + 1] = __floats2half2_rn(dis * v23.x, dis * v23.y);
        } else {
            float4 o = make_float4(v01.x, v01.y, v23.x, v23.y);
            *(float4*)&out[(size_t)row * 64 + c0] = o;
        }
    }
}

// ---------------------------------------------------------------------------
extern "C" void kernel_launch(void* const* d_in, const int* in_sizes, int n_in,
                              void* d_out, int out_size) {
    const float* H  = (const float*)d_in[0];
    const int*   ei = (const int*)  d_in[1];
    const float* m  = (const float*)d_in[2];
    const float* W  = (const float*)d_in[3];
    float* out = (float*)d_out;

    scatter_k<<<(BB * EE) / 256, 256>>>(ei, m);
    dedup_k<<<ROWS / 8, 256>>>(H);
    spmm_k<<<ROWS / 4, 256>>>(0);                       // g_x  -> g_pre
    gemm_k<<<ROWS / BR, 256>>>(W, nullptr, 0);          // g_pre -> g_x1 (GELU)
    spmm_k<<<ROWS / 4, 256>>>(1);                       // g_x1 -> g_pre
    gemm_k<<<ROWS / BR, 256>>>(W + DD * DD, out, 1);    // g_pre -> out
}

// round 10
// speedup vs baseline: 1.1705x; 1.1705x over previous
#include <cuda_runtime.h>
#include <cuda_fp16.h>
#include <math.h>

// Problem constants (fixed-shape problem)
#define BB   16
#define NN   2048
#define DD   64
#define EE   32768
#define MAXK 128
#define ROWS (BB*NN)          // 32768
#define TBL  128
#define BR   64               // rows per gemm block

// Scratch (device globals; zero-initialized at module load; no allocation)
__device__ int      g_cnt_raw[ROWS];                 // scatter counters (reset by dedup)
__device__ int      g_nnz[ROWS];                     // padded row sizes (multiple of 8)
__device__ uint2    g_bucket[(size_t)ROWS * MAXK];   // 32 MB (col<<17|pri, m_bits)
__device__ float    g_dis[ROWS];
__device__ uint2    g_adj[(size_t)ROWS * MAXK];      // 32 MB (col<<7 byte-off, m_bits)
__device__ __half2  g_x [(size_t)ROWS * 32];         // 4 MB: dis ⊙ H   (layer 0 input)
__device__ __half2  g_x1[(size_t)ROWS * 32];         // 4 MB: dis ⊙ x1  (layer 1 input)
__device__ float2   g_pre[(size_t)ROWS * 32];        // 8 MB: dis_r * (A·X~ + X~row)

// ---- packed f32x2 helpers (Blackwell) --------------------------------------
__device__ __forceinline__ unsigned long long splat2(float x) {
    unsigned long long r;
    asm("mov.b64 %0, {%1, %1};" : "=l"(r) : "r"(__float_as_uint(x)));
    return r;
}
__device__ __forceinline__ void fma2(unsigned long long& d,
                                     unsigned long long a, unsigned long long b) {
    asm("fma.rn.f32x2 %0, %1, %2, %0;" : "+l"(d) : "l"(a), "l"(b));
}
__device__ __forceinline__ float2 unpack2(unsigned long long v) {
    unsigned lo, hi;
    asm("mov.b64 {%0, %1}, %2;" : "=r"(lo), "=r"(hi) : "l"(v));
    return make_float2(__uint_as_float(lo), __uint_as_float(hi));
}

// ---------------------------------------------------------------------------
// scatter directed entries into per-row buckets, carrying m (coalesced read).
// key = (col << 17) | priority, priority = pass*E + e (pass2 > pass1)
__global__ void scatter_k(const int* __restrict__ ei, const float* __restrict__ m) {
    int t = blockIdx.x * blockDim.x + threadIdx.x;
    int b = t >> 15;
    int e = t & (EE - 1);
    int src = ei[b * 2 * EE + e];
    int dst = ei[b * 2 * EE + EE + e];
    unsigned mbits = __float_as_uint(m[t]);

    int r1 = b * NN + src;
    int p1 = atomicAdd(&g_cnt_raw[r1], 1);
    if (p1 < MAXK)
        g_bucket[(size_t)r1 * MAXK + p1] = make_uint2(((unsigned)dst << 17) | (unsigned)e, mbits);

    int r2 = b * NN + dst;
    int p2 = atomicAdd(&g_cnt_raw[r2], 1);
    if (p2 < MAXK)
        g_bucket[(size_t)r2 * MAXK + p2] = make_uint2(((unsigned)src << 17) | (unsigned)(EE + e), mbits);
}

// ---------------------------------------------------------------------------
// O(k) hash dedup (exact .set last-write-wins via 64-bit atomicMax on
// (col<<17|pri) in high word), ballot compaction into zero-padded CSR storing
// BYTE OFFSETS (col*128), deg -> dis = rsqrt(deg), AND prep: g_x = half(dis ⊙ H).
// Resets g_cnt_raw. One warp per row, 8 rows per block.
__global__ void __launch_bounds__(256) dedup_k(const float* __restrict__ H) {
    __shared__ unsigned long long tbl[8][TBL];
    int wid  = threadIdx.x >> 5, lane = threadIdx.x & 31;
    int row  = blockIdx.x * 8 + wid;

    for (int i = lane; i < TBL; i += 32) tbl[wid][i] = 0ULL;
    __syncwarp();

    int k = g_cnt_raw[row];
    if (k > MAXK) k = MAXK;
    const uint2* src = &g_bucket[(size_t)row * MAXK];
    for (int t = lane; t < k; t += 32) {
        uint2 v = src[t];
        unsigned col = v.x >> 17;
        unsigned long long val = ((unsigned long long)v.x << 32) | (unsigned long long)v.y;
        unsigned h = col & (TBL - 1);
        while (true) {
            unsigned long long cur = tbl[wid][h];
            if (cur == 0ULL) {
                unsigned long long old = atomicCAS(&tbl[wid][h], 0ULL, val);
                if (old == 0ULL) break;
                cur = old;
            }
            if ((unsigned)(cur >> 49) == col) {       // same col -> keep max priority
                atomicMax(&tbl[wid][h], val);
                break;
            }
            h = (h + 1) & (TBL - 1);
        }
    }
    __syncwarp();

    // compact + degree sum; store byte offset col*128 (fp16 row = 128B)
    float deg = 0.f;
    int base = 0;
    uint2* dst = &g_adj[(size_t)row * MAXK];
    #pragma unroll
    for (int s0 = 0; s0 < TBL; s0 += 32) {
        unsigned long long cur = tbl[wid][s0 + lane];
        bool has = (cur != 0ULL);
        unsigned bal = __ballot_sync(0xFFFFFFFFu, has);
        if (has) {
            int pos = base + __popc(bal & ((1u << lane) - 1));
            unsigned col = ((unsigned)(cur >> 32)) >> 17;
            unsigned mb  = (unsigned)cur;
            dst[pos] = make_uint2(col << 7, mb);
            deg += __uint_as_float(mb);
        }
        base += __popc(bal);
    }
    // zero padding up to multiple of 8 (beyond stays zero from static init;
    // replays rewrite identical data so zero region is invariant)
    int pad = (base + 7) & ~7;
    if (base + lane < pad) dst[base + lane] = make_uint2(0u, 0u);

    // all-lanes deg reduction -> dis on every lane
    #pragma unroll
    for (int o = 16; o; o >>= 1) deg += __shfl_xor_sync(0xFFFFFFFFu, deg, o);
    float dis = rsqrtf(fmaxf(1.0f + deg, 1e-6f));

    // prep: g_x[row] = half(dis * H[row])
    const float2* Hrow = (const float2*)H + row * 32;
    float2 h2 = Hrow[lane];
    g_x[row * 32 + lane] = __floats2half2_rn(dis * h2.x, dis * h2.y);

    if (lane == 0) {
        g_nnz[row] = pad;
        g_dis[row] = dis;
        g_cnt_raw[row] = 0;     // ready for next replay
    }
}

// ---------------------------------------------------------------------------
// SpMM phase: pre[row] = dis_r * (sum_e m_e * X~[col] + X~[row]).
// TWO rows per warp, fully interleaved in registers (no smem, no sync, no
// branches): 16 independent gathers + 8 uniform LDG.128 in flight per warp.
// Both rows run to max(n0,n1); pad entries are (0,0) -> w=0 no-ops.
__global__ void __launch_bounds__(256) spmm_k(int stage) {
    const __half2* Xin = (stage == 0) ? g_x : g_x1;
    int wid = threadIdx.x >> 5, lane = threadIdx.x & 31;
    int row0 = (blockIdx.x * 8 + wid) * 2;
    int row1 = row0 + 1;

    const char* XbL = (const char*)(Xin + (row0 & ~(NN - 1)) * 32) + lane * 4;
    float2 a0 = __half22float2(Xin[row0 * 32 + lane]);   // diag term X~row0
    float2 a1 = __half22float2(Xin[row1 * 32 + lane]);   // diag term X~row1
    const uint2* ar0 = &g_adj[(size_t)row0 * MAXK];
    const uint2* ar1 = ar0 + MAXK;
    int n = max(g_nnz[row0], g_nnz[row1]);               // <= MAXK, multiple of 8

    for (int k = 0; k < n; k += 8) {
        uint4 e0 = *(const uint4*)(ar0 + k);
        uint4 e1 = *(const uint4*)(ar0 + k + 2);
        uint4 e2 = *(const uint4*)(ar0 + k + 4);
        uint4 e3 = *(const uint4*)(ar0 + k + 6);
        uint4 g0 = *(const uint4*)(ar1 + k);
        uint4 g1 = *(const uint4*)(ar1 + k + 2);
        uint4 g2 = *(const uint4*)(ar1 + k + 4);
        uint4 g3 = *(const uint4*)(ar1 + k + 6);

        __half2 x0 = *(const __half2*)(XbL + e0.x);
        __half2 x1 = *(const __half2*)(XbL + e0.z);
        __half2 x2 = *(const __half2*)(XbL + e1.x);
        __half2 x3 = *(const __half2*)(XbL + e1.z);
        __half2 x4 = *(const __half2*)(XbL + e2.x);
        __half2 x5 = *(const __half2*)(XbL + e2.z);
        __half2 x6 = *(const __half2*)(XbL + e3.x);
        __half2 x7 = *(const __half2*)(XbL + e3.z);
        __half2 y0 = *(const __half2*)(XbL + g0.x);
        __half2 y1 = *(const __half2*)(XbL + g0.z);
        __half2 y2 = *(const __half2*)(XbL + g1.x);
        __half2 y3 = *(const __half2*)(XbL + g1.z);
        __half2 y4 = *(const __half2*)(XbL + g2.x);
        __half2 y5 = *(const __half2*)(XbL + g2.z);
        __half2 y6 = *(const __half2*)(XbL + g3.x);
        __half2 y7 = *(const __half2*)(XbL + g3.z);

        float2 f;
        f = __half22float2(x0); a0.x += __uint_as_float(e0.y) * f.x; a0.y += __uint_as_float(e0.y) * f.y;
        f = __half22float2(x1); a0.x += __uint_as_float(e0.w) * f.x; a0.y += __uint_as_float(e0.w) * f.y;
        f = __half22float2(x2); a0.x += __uint_as_float(e1.y) * f.x; a0.y += __uint_as_float(e1.y) * f.y;
        f = __half22float2(x3); a0.x += __uint_as_float(e1.w) * f.x; a0.y += __uint_as_float(e1.w) * f.y;
        f = __half22float2(x4); a0.x += __uint_as_float(e2.y) * f.x; a0.y += __uint_as_float(e2.y) * f.y;
        f = __half22float2(x5); a0.x += __uint_as_float(e2.w) * f.x; a0.y += __uint_as_float(e2.w) * f.y;
        f = __half22float2(x6); a0.x += __uint_as_float(e3.y) * f.x; a0.y += __uint_as_float(e3.y) * f.y;
        f = __half22float2(x7); a0.x += __uint_as_float(e3.w) * f.x; a0.y += __uint_as_float(e3.w) * f.y;
        f = __half22float2(y0); a1.x += __uint_as_float(g0.y) * f.x; a1.y += __uint_as_float(g0.y) * f.y;
        f = __half22float2(y1); a1.x += __uint_as_float(g0.w) * f.x; a1.y += __uint_as_float(g0.w) * f.y;
        f = __half22float2(y2); a1.x += __uint_as_float(g1.y) * f.x; a1.y += __uint_as_float(g1.y) * f.y;
        f = __half22float2(y3); a1.x += __uint_as_float(g1.w) * f.x; a1.y += __uint_as_float(g1.w) * f.y;
        f = __half22float2(y4); a1.x += __uint_as_float(g2.y) * f.x; a1.y += __uint_as_float(g2.y) * f.y;
        f = __half22float2(y5); a1.x += __uint_as_float(g2.w) * f.x; a1.y += __uint_as_float(g2.w) * f.y;
        f = __half22float2(y6); a1.x += __uint_as_float(g3.y) * f.x; a1.y += __uint_as_float(g3.y) * f.y;
        f = __half22float2(y7); a1.x += __uint_as_float(g3.w) * f.x; a1.y += __uint_as_float(g3.w) * f.y;
    }
    float d0 = g_dis[row0];
    float d1 = g_dis[row1];
    g_pre[row0 * 32 + lane] = make_float2(d0 * a0.x, d0 * a0.y);
    g_pre[row1 * 32 + lane] = make_float2(d1 * a1.x, d1 * a1.y);
}

// ---------------------------------------------------------------------------
// Dense GEMM phase (R8 config): v = pre @ W^T, then (stage 0)
// g_x1 = half(dis * gelu(v)) or (stage 1) out = v. 64 rows/block, 256 threads,
// thread owns 4x4 outputs, packed fma.rn.f32x2 inner loop.
__global__ void __launch_bounds__(256) gemm_k(const float* __restrict__ Wl,
                                              float* __restrict__ out,
                                              int stage) {
    __shared__ float sP[BR][68];    // pre tile, row-major [r][d], padded
    __shared__ float sW[64][68];    // W transposed [d][e], padded
    int tid = threadIdx.x;
    int row0 = blockIdx.x * BR;

    // W[e][d] -> sW[d][e]  (coalesced gmem read)
    for (int idx = tid; idx < 4096; idx += 256) {
        int e = idx >> 6, d = idx & 63;
        sW[d][e] = Wl[idx];
    }
    // pre tile: straight float4 copy (row-major, no transpose)
    const float4* P = (const float4*)(g_pre + (size_t)row0 * 32);
    for (int idx = tid; idx < BR * 16; idx += 256) {
        int r = idx >> 4, d4 = idx & 15;
        *(float4*)&sP[r][d4 * 4] = P[idx];
    }
    __syncthreads();

    int rg = tid >> 4, cg = tid & 15;
    int r0 = rg * 4, c0 = cg * 4;

    unsigned long long acc[4][2];
    #pragma unroll
    for (int r = 0; r < 4; r++) { acc[r][0] = 0ULL; acc[r][1] = 0ULL; }

    #pragma unroll
    for (int d0 = 0; d0 < 64; d0 += 4) {
        float4 p[4];
        #pragma unroll
        for (int r = 0; r < 4; r++)
            p[r] = *(const float4*)&sP[r0 + r][d0];
        #pragma unroll
        for (int dd = 0; dd < 4; dd++) {
            unsigned long long w01 = *(const unsigned long long*)&sW[d0 + dd][c0];
            unsigned long long w23 = *(const unsigned long long*)&sW[d0 + dd][c0 + 2];
            #pragma unroll
            for (int r = 0; r < 4; r++) {
                unsigned long long s = splat2((&p[r].x)[dd]);
                fma2(acc[r][0], s, w01);
                fma2(acc[r][1], s, w23);
            }
        }
    }

    #pragma unroll
    for (int r = 0; r < 4; r++) {
        int row = row0 + r0 + r;
        float2 v01 = unpack2(acc[r][0]);
        float2 v23 = unpack2(acc[r][1]);
        if (stage == 0) {
            // exact GELU, prescale by dis, store fp16 for next layer's gather
            float dis = g_dis[row];
            v01.x = 0.5f * v01.x * (1.f + erff(v01.x * 0.70710678118654752f));
            v01.y = 0.5f * v01.y * (1.f + erff(v01.y * 0.70710678118654752f));
            v23.x = 0.5f * v23.x * (1.f + erff(v23.x * 0.70710678118654752f));
            v23.y = 0.5f * v23.y * (1.f + erff(v23.y * 0.70710678118654752f));
            g_x1[row * 32 + (c0 >> 1)]     = __floats2half2_rn(dis * v01.x, dis * v01.y);
            g_x1[row * 32 + (c0 >> 1) + 1] = __floats2half2_rn(dis * v23.x, dis * v23.y);
        } else {
            float4 o = make_float4(v01.x, v01.y, v23.x, v23.y);
            *(float4*)&out[(size_t)row * 64 + c0] = o;
        }
    }
}

// ---------------------------------------------------------------------------
extern "C" void kernel_launch(void* const* d_in, const int* in_sizes, int n_in,
                              void* d_out, int out_size) {
    const float* H  = (const float*)d_in[0];
    const int*   ei = (const int*)  d_in[1];
    const float* m  = (const float*)d_in[2];
    const float* W  = (const float*)d_in[3];
    float* out = (float*)d_out;

    scatter_k<<<(BB * EE) / 256, 256>>>(ei, m);
    dedup_k<<<ROWS / 8, 256>>>(H);
    spmm_k<<<ROWS / 16, 256>>>(0);                      // g_x  -> g_pre
    gemm_k<<<ROWS / BR, 256>>>(W, nullptr, 0);          // g_pre -> g_x1 (GELU)
    spmm_k<<<ROWS / 16, 256>>>(1);                      // g_x1 -> g_pre
    gemm_k<<<ROWS / BR, 256>>>(W + DD * DD, out, 1);    // g_pre -> out
}